// round 9
// baseline (speedup 1.0000x reference)
#include <cuda_runtime.h>
#include <math.h>

#define N_NODES 50000
#define N_EDGES 400000
#define F_DIM   128
#define N_TYPES 100
#define N_RBF   20
#define CUTOFF  5.0f
#define F3      (3 * F_DIM)   // 384

#define SCAN_B  256
#define SCAN_NB ((N_NODES + SCAN_B - 1) / SCAN_B)   // 196
#define HIST_NB ((N_EDGES + 255) / 256)             // 1563
#define PHI_NB  (N_TYPES / 2)                       // 50

typedef unsigned long long ull;

// -------- device scratch (no allocations allowed; zero-initialized at load) --------
__device__ int   g_count[N_NODES];        // re-zeroed by scan_kernel each call
__device__ int   g_start[N_NODES + 1];
__device__ int   g_cursor[N_NODES];
__device__ ull   g_scan_state[SCAN_NB];   // re-zeroed by sg_kernel each call
__device__ float g_phi[N_TYPES * F3];     // 100 x 384

// per-edge packed row (dst-sorted order): [0..19]=rbf, [20..22]=rel*dist,
// [23]=pad, [24]=src bits, [25]=typ bits, [26..31]=pad  => 128 bytes
struct __align__(16) EdgeRow { float v[32]; };
__device__ EdgeRow g_edat[N_EDGES];       // 51.2 MB

// ---------------------------------------------------------
// Launch 0 (pre): hist blocks count edge_dst; phi blocks compute the MLP table.
__global__ void pre_kernel(const int* __restrict__ edge_dst,
                           const float* __restrict__ emb_table,
                           const float* __restrict__ w1, const float* __restrict__ b1,
                           const float* __restrict__ w2, const float* __restrict__ b2) {
    if (blockIdx.x < HIST_NB) {
        int e = blockIdx.x * 256 + threadIdx.x;
        if (e < N_EDGES) atomicAdd(&g_count[edge_dst[e]], 1);
        return;
    }
    // phi: 2 atom types per block (each 128-thread half does one type)
    int bb = blockIdx.x - HIST_NB;          // 0..49
    int half = threadIdx.x >> 7;            // 0/1
    int t = bb * 2 + half;                  // atom type
    int f = threadIdx.x & 127;
    __shared__ float es[2][F_DIM];
    __shared__ float hs[2][F_DIM];
    es[half][f] = emb_table[t * F_DIM + f];
    __syncthreads();
    float h = b1[f];
#pragma unroll 8
    for (int k = 0; k < F_DIM; k++)
        h = fmaf(es[half][k], w1[k * F_DIM + f], h);
    h = h / (1.0f + expf(-h));   // silu
    hs[half][f] = h;
    __syncthreads();
    float o0 = b2[f], o1 = b2[F_DIM + f], o2 = b2[2 * F_DIM + f];
#pragma unroll 8
    for (int k = 0; k < F_DIM; k++) {
        float hk = hs[half][k];
        const float* w2r = w2 + k * F3;
        o0 = fmaf(hk, w2r[f],             o0);
        o1 = fmaf(hk, w2r[F_DIM + f],     o1);
        o2 = fmaf(hk, w2r[2 * F_DIM + f], o2);
    }
    g_phi[t * F3 + f]             = o0;
    g_phi[t * F3 + F_DIM + f]     = o1;
    g_phi[t * F3 + 2 * F_DIM + f] = o2;
}

// ---------------------------------------------------------
// Launch 1: decoupled-lookback exclusive scan of g_count -> g_start, g_cursor.
// Also re-zeroes g_count for the next call (only the owning thread reads it).
__global__ void scan_kernel() {
    __shared__ int wsum[SCAN_B / 32];
    __shared__ int s_prefix;
    int t = threadIdx.x;
    int b = blockIdx.x;
    int i = b * SCAN_B + t;
    int v = 0;
    if (i < N_NODES) {
        v = g_count[i];
        g_count[i] = 0;          // reset for next call's histogram
    }

    // block-local inclusive scan
    int sv = v;
    for (int off = 1; off < 32; off <<= 1) {
        int u = __shfl_up_sync(0xffffffffu, sv, off);
        if ((t & 31) >= off) sv += u;
    }
    if ((t & 31) == 31) wsum[t >> 5] = sv;
    __syncthreads();
    if (t < SCAN_B / 32) {
        int s = wsum[t];
        for (int off = 1; off < SCAN_B / 32; off <<= 1) {
            int u = __shfl_up_sync(0xffu, s, off);
            if (t >= off) s += u;
        }
        wsum[t] = s;
    }
    __syncthreads();
    int warp = t >> 5;
    int incl = sv + ((warp > 0) ? wsum[warp - 1] : 0);
    int total = wsum[SCAN_B / 32 - 1];

    // decoupled lookback (thread 0)
    if (t == 0) {
        if (b == 0) {
            atomicExch(&g_scan_state[0], ((ull)total << 2) | 2ULL);
            s_prefix = 0;
            g_start[N_NODES] = N_EDGES;
        } else {
            atomicExch(&g_scan_state[b], ((ull)total << 2) | 1ULL);
            int prefix = 0;
            int j = b - 1;
            while (j >= 0) {
                ull st;
                do { st = atomicAdd(&g_scan_state[j], 0ULL); } while ((st & 3ULL) == 0ULL);
                prefix += (int)(st >> 2);
                if ((st & 3ULL) == 2ULL) break;
                j--;
            }
            atomicExch(&g_scan_state[b], ((ull)(prefix + total) << 2) | 2ULL);
            s_prefix = prefix;
        }
    }
    __syncthreads();
    int excl = s_prefix + incl - v;
    if (i < N_NODES) {
        g_start[i]  = excl;
        g_cursor[i] = excl;
    }
}

// ---------------------------------------------------------
// Launch 2: fused scatter + geometry. Each thread claims its dst-sorted slot
// and writes the complete 128-byte edge row. Also re-zeroes g_scan_state
// (scan of THIS call is already complete; next call needs it zeroed).
__global__ void sg_kernel(const float* __restrict__ pos,
                          const int*   __restrict__ z,
                          const int*   __restrict__ edge_src,
                          const int*   __restrict__ edge_dst) {
    int e = blockIdx.x * blockDim.x + threadIdx.x;
    if (e < SCAN_NB) g_scan_state[e] = 0ULL;
    if (e >= N_EDGES) return;
    int s = __ldg(&edge_src[e]);
    int d = __ldg(&edge_dst[e]);
    int p = atomicAdd(&g_cursor[d], 1);
    int ty = __ldg(&z[s]);
    float rx = __ldg(&pos[d * 3 + 0]) - __ldg(&pos[s * 3 + 0]);
    float ry = __ldg(&pos[d * 3 + 1]) - __ldg(&pos[s * 3 + 1]);
    float rz = __ldg(&pos[d * 3 + 2]) - __ldg(&pos[s * 3 + 2]);
    float dist = sqrtf(rx * rx + ry * ry + rz * rz);
    float inv  = 1.0f / dist;

    float row[32];
    float a = 3.14159265358979323846f * dist * (1.0f / CUTOFF);
    float s1, c1;
    sincosf(a, &s1, &c1);
    float twoc = 2.0f * c1;
    float sp = 0.0f, sc = s1;          // sin(0), sin(a)
#pragma unroll
    for (int k = 0; k < N_RBF; k++) {  // sin((k+1)a), stable Chebyshev recurrence
        row[k] = sc * inv;
        float nx = twoc * sc - sp;
        sp = sc; sc = nx;
    }
    row[20] = rx * dist;
    row[21] = ry * dist;
    row[22] = rz * dist;
    row[23] = 0.0f;
    row[24] = __int_as_float(s);
    row[25] = __int_as_float(ty);
    row[26] = row[27] = row[28] = row[29] = row[30] = row[31] = 0.0f;

    float4* dst4 = reinterpret_cast<float4*>(g_edat[p].v);
    const float4* src4 = reinterpret_cast<const float4*>(row);
#pragma unroll
    for (int j = 0; j < 8; j++) dst4[j] = src4[j];
}

// ---------------------------------------------------------
// Launch 3 (PROFILED): main. One block (128 threads) per destination node.
// launch_bounds(128,6): 85-reg cap -> 24 resident warps/SM (occupancy lever).
__global__ __launch_bounds__(128, 6)
void main_kernel(const float* __restrict__ eq,
                 const float* __restrict__ emb_table,
                 const float* __restrict__ w_rbf,
                 const float* __restrict__ b_rbf,
                 const int*   __restrict__ z,
                 float* __restrict__ out_emb,
                 float* __restrict__ out_eq) {
    int f = threadIdx.x;
    int node = blockIdx.x;

    int e0 = g_start[node];
    int e1 = __ldg(&g_start[node + 1]);
    int zi = __ldg(&z[node]);

    // per-thread w_rbf columns in registers (60 regs)
    float wr0[N_RBF], wr1[N_RBF], wr2[N_RBF];
#pragma unroll
    for (int k = 0; k < N_RBF; k++) {
        const float* row = w_rbf + k * F3;
        wr0[k] = row[f];
        wr1[k] = row[F_DIM + f];
        wr2[k] = row[2 * F_DIM + f];
    }
    const float br0 = b_rbf[f], br1 = b_rbf[F_DIM + f], br2 = b_rbf[2 * F_DIM + f];

    __shared__ __align__(16) float sh_rbf[128][N_RBF];
    __shared__ float sh_rd[128][3];
    __shared__ int   sh_src[128];
    __shared__ int   sh_typ[128];

    int cnt = e1 - e0;
    float acc0 = 0.f, aq0 = 0.f, aq1 = 0.f, aq2 = 0.f;

    for (int base = 0; base < cnt; base += 128) {
        int nch = min(128, cnt - base);
        // phase 1: bulk-load pre-staged rows (independent 128B loads)
        if (f < nch) {
            const float4* row = reinterpret_cast<const float4*>(g_edat[e0 + base + f].v);
            float4 a0 = __ldg(row + 0);
            float4 a1 = __ldg(row + 1);
            float4 a2 = __ldg(row + 2);
            float4 a3 = __ldg(row + 3);
            float4 a4 = __ldg(row + 4);
            float4 rd = __ldg(row + 5);
            float4 mt = __ldg(row + 6);
            float4* rb4 = reinterpret_cast<float4*>(sh_rbf[f]);
            rb4[0] = a0; rb4[1] = a1; rb4[2] = a2; rb4[3] = a3; rb4[4] = a4;
            sh_rd[f][0] = rd.x;
            sh_rd[f][1] = rd.y;
            sh_rd[f][2] = rd.z;
            sh_src[f] = __float_as_int(mt.x);
            sh_typ[f] = __float_as_int(mt.y);
        }
        __syncthreads();
        // phase 2: all 128 threads accumulate over the chunk's edges
#pragma unroll 2
        for (int e = 0; e < nch; e++) {
            const float* ph = g_phi + sh_typ[e] * F3;
            int s = sh_src[e];
            const float* eqs = eq + (size_t)s * F3 + f * 3;
            float p0 = ph[f];
            float p1 = ph[F_DIM + f];
            float p2 = ph[2 * F_DIM + f];
            float eq0 = eqs[0], eq1 = eqs[1], eq2 = eqs[2];
            float W0 = br0, W1 = br1, W2 = br2;
#pragma unroll
            for (int k = 0; k < N_RBF; k++) {
                float r = sh_rbf[e][k];    // broadcast
                W0 = fmaf(r, wr0[k], W0);
                W1 = fmaf(r, wr1[k], W1);
                W2 = fmaf(r, wr2[k], W2);
            }
            float s1v = p1 * W1;
            float s2v = p2 * W2;
            acc0 = fmaf(p0, W0, acc0);
            aq0 = fmaf(eq0, s1v, fmaf(s2v, sh_rd[e][0], aq0));
            aq1 = fmaf(eq1, s1v, fmaf(s2v, sh_rd[e][1], aq1));
            aq2 = fmaf(eq2, s1v, fmaf(s2v, sh_rd[e][2], aq2));
        }
        __syncthreads();
    }

    // epilogue: out = input + delta (written exactly once, no atomics)
    out_emb[node * F_DIM + f] = emb_table[zi * F_DIM + f] + acc0;
    float*       oe = out_eq + (size_t)node * F3 + f * 3;
    const float* ei = eq     + (size_t)node * F3 + f * 3;
    oe[0] = ei[0] + aq0;
    oe[1] = ei[1] + aq1;
    oe[2] = ei[2] + aq2;
}

// ---------------------------------------------------------
extern "C" void kernel_launch(void* const* d_in, const int* in_sizes, int n_in,
                              void* d_out, int out_size) {
    const float* pos       = (const float*)d_in[0];
    const float* eq        = (const float*)d_in[1];
    const float* emb_table = (const float*)d_in[2];
    const float* w_phi1    = (const float*)d_in[3];
    const float* b_phi1    = (const float*)d_in[4];
    const float* w_phi2    = (const float*)d_in[5];
    const float* b_phi2    = (const float*)d_in[6];
    const float* w_rbf     = (const float*)d_in[7];
    const float* b_rbf     = (const float*)d_in[8];
    const int*   z         = (const int*)d_in[9];
    const int*   edge_src  = (const int*)d_in[10];
    const int*   edge_dst  = (const int*)d_in[11];

    float* out     = (float*)d_out;
    float* out_emb = out;                                  // [N, 128]
    float* out_eq  = out + (size_t)N_NODES * F_DIM;        // [N, 128, 3]

    pre_kernel<<<HIST_NB + PHI_NB, 256>>>(edge_dst, emb_table, w_phi1, b_phi1,
                                          w_phi2, b_phi2);
    scan_kernel<<<SCAN_NB, SCAN_B>>>();
    sg_kernel<<<HIST_NB, 256>>>(pos, z, edge_src, edge_dst);
    main_kernel<<<N_NODES, 128>>>(eq, emb_table, w_rbf, b_rbf, z,
                                  out_emb, out_eq);
}

// round 10
// speedup vs baseline: 1.2362x; 1.2362x over previous
#include <cuda_runtime.h>
#include <math.h>

#define N_NODES 50000
#define N_EDGES 400000
#define F_DIM   128
#define N_TYPES 100
#define N_RBF   20
#define CUTOFF  5.0f
#define F3      (3 * F_DIM)   // 384

#define SCAN_B  256
#define SCAN_NB ((N_NODES + SCAN_B - 1) / SCAN_B)   // 196
#define HIST_NB ((N_EDGES + 255) / 256)             // 1563
#define PHI_NB  (N_TYPES / 2)                       // 50

typedef unsigned long long ull;

// -------- device scratch (no allocations allowed; zero-initialized at load) --------
__device__ int   g_count[N_NODES];        // re-zeroed by scan_kernel each call
__device__ int   g_start[N_NODES + 1];
__device__ int   g_cursor[N_NODES];
__device__ ull   g_scan_state[SCAN_NB];   // re-zeroed by sg_kernel each call
__device__ float g_phi[N_TYPES * F3];     // 100 x 384

// per-edge packed row (dst-sorted order): [0..19]=rbf, [20..22]=rel*dist,
// [23]=pad, [24]=src bits, [25]=typ bits, [26..31]=pad  => 128 bytes
struct __align__(16) EdgeRow { float v[32]; };
__device__ EdgeRow g_edat[N_EDGES];       // 51.2 MB

// ---------------------------------------------------------
// Launch 0 (pre): hist blocks count edge_dst; phi blocks compute the MLP table.
__global__ void pre_kernel(const int* __restrict__ edge_dst,
                           const float* __restrict__ emb_table,
                           const float* __restrict__ w1, const float* __restrict__ b1,
                           const float* __restrict__ w2, const float* __restrict__ b2) {
    if (blockIdx.x < HIST_NB) {
        int e = blockIdx.x * 256 + threadIdx.x;
        if (e < N_EDGES) atomicAdd(&g_count[edge_dst[e]], 1);
        return;
    }
    // phi: 2 atom types per block (each 128-thread half does one type)
    int bb = blockIdx.x - HIST_NB;          // 0..49
    int half = threadIdx.x >> 7;            // 0/1
    int t = bb * 2 + half;                  // atom type
    int f = threadIdx.x & 127;
    __shared__ float es[2][F_DIM];
    __shared__ float hs[2][F_DIM];
    es[half][f] = emb_table[t * F_DIM + f];
    __syncthreads();
    float h = b1[f];
#pragma unroll 8
    for (int k = 0; k < F_DIM; k++)
        h = fmaf(es[half][k], w1[k * F_DIM + f], h);
    h = h / (1.0f + expf(-h));   // silu
    hs[half][f] = h;
    __syncthreads();
    float o0 = b2[f], o1 = b2[F_DIM + f], o2 = b2[2 * F_DIM + f];
#pragma unroll 8
    for (int k = 0; k < F_DIM; k++) {
        float hk = hs[half][k];
        const float* w2r = w2 + k * F3;
        o0 = fmaf(hk, w2r[f],             o0);
        o1 = fmaf(hk, w2r[F_DIM + f],     o1);
        o2 = fmaf(hk, w2r[2 * F_DIM + f], o2);
    }
    g_phi[t * F3 + f]             = o0;
    g_phi[t * F3 + F_DIM + f]     = o1;
    g_phi[t * F3 + 2 * F_DIM + f] = o2;
}

// ---------------------------------------------------------
// Launch 1: decoupled-lookback exclusive scan of g_count -> g_start, g_cursor.
// Also re-zeroes g_count for the next call.
__global__ void scan_kernel() {
    __shared__ int wsum[SCAN_B / 32];
    __shared__ int s_prefix;
    int t = threadIdx.x;
    int b = blockIdx.x;
    int i = b * SCAN_B + t;
    int v = 0;
    if (i < N_NODES) {
        v = g_count[i];
        g_count[i] = 0;
    }

    int sv = v;
    for (int off = 1; off < 32; off <<= 1) {
        int u = __shfl_up_sync(0xffffffffu, sv, off);
        if ((t & 31) >= off) sv += u;
    }
    if ((t & 31) == 31) wsum[t >> 5] = sv;
    __syncthreads();
    if (t < SCAN_B / 32) {
        int s = wsum[t];
        for (int off = 1; off < SCAN_B / 32; off <<= 1) {
            int u = __shfl_up_sync(0xffu, s, off);
            if (t >= off) s += u;
        }
        wsum[t] = s;
    }
    __syncthreads();
    int warp = t >> 5;
    int incl = sv + ((warp > 0) ? wsum[warp - 1] : 0);
    int total = wsum[SCAN_B / 32 - 1];

    if (t == 0) {
        if (b == 0) {
            atomicExch(&g_scan_state[0], ((ull)total << 2) | 2ULL);
            s_prefix = 0;
            g_start[N_NODES] = N_EDGES;
        } else {
            atomicExch(&g_scan_state[b], ((ull)total << 2) | 1ULL);
            int prefix = 0;
            int j = b - 1;
            while (j >= 0) {
                ull st;
                do { st = atomicAdd(&g_scan_state[j], 0ULL); } while ((st & 3ULL) == 0ULL);
                prefix += (int)(st >> 2);
                if ((st & 3ULL) == 2ULL) break;
                j--;
            }
            atomicExch(&g_scan_state[b], ((ull)(prefix + total) << 2) | 2ULL);
            s_prefix = prefix;
        }
    }
    __syncthreads();
    int excl = s_prefix + incl - v;
    if (i < N_NODES) {
        g_start[i]  = excl;
        g_cursor[i] = excl;
    }
}

// ---------------------------------------------------------
// Launch 2: fused scatter + geometry; also re-zeroes g_scan_state.
__global__ void sg_kernel(const float* __restrict__ pos,
                          const int*   __restrict__ z,
                          const int*   __restrict__ edge_src,
                          const int*   __restrict__ edge_dst) {
    int e = blockIdx.x * blockDim.x + threadIdx.x;
    if (e < SCAN_NB) g_scan_state[e] = 0ULL;
    if (e >= N_EDGES) return;
    int s = __ldg(&edge_src[e]);
    int d = __ldg(&edge_dst[e]);
    int p = atomicAdd(&g_cursor[d], 1);
    int ty = __ldg(&z[s]);
    float rx = __ldg(&pos[d * 3 + 0]) - __ldg(&pos[s * 3 + 0]);
    float ry = __ldg(&pos[d * 3 + 1]) - __ldg(&pos[s * 3 + 1]);
    float rz = __ldg(&pos[d * 3 + 2]) - __ldg(&pos[s * 3 + 2]);
    float dist = sqrtf(rx * rx + ry * ry + rz * rz);
    float inv  = 1.0f / dist;

    float row[32];
    float a = 3.14159265358979323846f * dist * (1.0f / CUTOFF);
    float s1, c1;
    sincosf(a, &s1, &c1);
    float twoc = 2.0f * c1;
    float sp = 0.0f, sc = s1;          // sin(0), sin(a)
#pragma unroll
    for (int k = 0; k < N_RBF; k++) {  // sin((k+1)a), stable Chebyshev recurrence
        row[k] = sc * inv;
        float nx = twoc * sc - sp;
        sp = sc; sc = nx;
    }
    row[20] = rx * dist;
    row[21] = ry * dist;
    row[22] = rz * dist;
    row[23] = 0.0f;
    row[24] = __int_as_float(s);
    row[25] = __int_as_float(ty);
    row[26] = row[27] = row[28] = row[29] = row[30] = row[31] = 0.0f;

    float4* dst4 = reinterpret_cast<float4*>(g_edat[p].v);
    const float4* src4 = reinterpret_cast<const float4*>(row);
#pragma unroll
    for (int j = 0; j < 8; j++) dst4[j] = src4[j];
}

// ---------------------------------------------------------
// Launch 3 (PROFILED): main. One block (128 threads) per destination node.
// Transposed smem rbf + 4-edge register blocking: 20 LDS.128 per edge-quad.
__global__ __launch_bounds__(128, 4)
void main_kernel(const float* __restrict__ eq,
                 const float* __restrict__ emb_table,
                 const float* __restrict__ w_rbf,
                 const float* __restrict__ b_rbf,
                 const int*   __restrict__ z,
                 float* __restrict__ out_emb,
                 float* __restrict__ out_eq) {
    int f = threadIdx.x;
    int node = blockIdx.x;

    int e0 = g_start[node];
    int e1 = __ldg(&g_start[node + 1]);
    int zi = __ldg(&z[node]);

    // per-thread w_rbf columns in registers (60 regs)
    float wr0[N_RBF], wr1[N_RBF], wr2[N_RBF];
#pragma unroll
    for (int k = 0; k < N_RBF; k++) {
        const float* row = w_rbf + k * F3;
        wr0[k] = row[f];
        wr1[k] = row[F_DIM + f];
        wr2[k] = row[2 * F_DIM + f];
    }
    const float br0 = b_rbf[f], br1 = b_rbf[F_DIM + f], br2 = b_rbf[2 * F_DIM + f];

    // transposed staging: [k][e] so 4 consecutive edges load as one LDS.128
    __shared__ __align__(16) float sh_rbf[N_RBF][128];
    __shared__ __align__(16) float sh_rd0[128], sh_rd1[128], sh_rd2[128];
    __shared__ __align__(16) int   sh_src[128];
    __shared__ __align__(16) int   sh_typ[128];

    int cnt = e1 - e0;
    float acc0 = 0.f, aq0 = 0.f, aq1 = 0.f, aq2 = 0.f;

    for (int base = 0; base < cnt; base += 128) {
        int nch = min(128, cnt - base);
        // phase 1: bulk-load pre-staged rows, transpose into smem
        if (f < nch) {
            const float4* row = reinterpret_cast<const float4*>(g_edat[e0 + base + f].v);
            float4 a0 = __ldg(row + 0);
            float4 a1 = __ldg(row + 1);
            float4 a2 = __ldg(row + 2);
            float4 a3 = __ldg(row + 3);
            float4 a4 = __ldg(row + 4);
            float4 rd = __ldg(row + 5);
            float4 mt = __ldg(row + 6);
            sh_rbf[0][f]  = a0.x; sh_rbf[1][f]  = a0.y; sh_rbf[2][f]  = a0.z; sh_rbf[3][f]  = a0.w;
            sh_rbf[4][f]  = a1.x; sh_rbf[5][f]  = a1.y; sh_rbf[6][f]  = a1.z; sh_rbf[7][f]  = a1.w;
            sh_rbf[8][f]  = a2.x; sh_rbf[9][f]  = a2.y; sh_rbf[10][f] = a2.z; sh_rbf[11][f] = a2.w;
            sh_rbf[12][f] = a3.x; sh_rbf[13][f] = a3.y; sh_rbf[14][f] = a3.z; sh_rbf[15][f] = a3.w;
            sh_rbf[16][f] = a4.x; sh_rbf[17][f] = a4.y; sh_rbf[18][f] = a4.z; sh_rbf[19][f] = a4.w;
            sh_rd0[f] = rd.x;
            sh_rd1[f] = rd.y;
            sh_rd2[f] = rd.z;
            sh_src[f] = __float_as_int(mt.x);
            sh_typ[f] = __float_as_int(mt.y);
        }
        __syncthreads();

        int nch4 = nch & ~3;
        // phase 2a: edge quads
        for (int e = 0; e < nch4; e += 4) {
            // hoisted per-quad loads (max MLP)
            int4 s4 = *reinterpret_cast<const int4*>(&sh_src[e]);
            int4 t4 = *reinterpret_cast<const int4*>(&sh_typ[e]);
            const float* phA = g_phi + t4.x * F3;
            const float* phB = g_phi + t4.y * F3;
            const float* phC = g_phi + t4.z * F3;
            const float* phD = g_phi + t4.w * F3;
            float pA0 = phA[f], pA1 = phA[F_DIM + f], pA2 = phA[2 * F_DIM + f];
            float pB0 = phB[f], pB1 = phB[F_DIM + f], pB2 = phB[2 * F_DIM + f];
            float pC0 = phC[f], pC1 = phC[F_DIM + f], pC2 = phC[2 * F_DIM + f];
            float pD0 = phD[f], pD1 = phD[F_DIM + f], pD2 = phD[2 * F_DIM + f];
            const float* eqA = eq + (size_t)s4.x * F3 + f * 3;
            const float* eqB = eq + (size_t)s4.y * F3 + f * 3;
            const float* eqC = eq + (size_t)s4.z * F3 + f * 3;
            const float* eqD = eq + (size_t)s4.w * F3 + f * 3;
            float eA0 = eqA[0], eA1 = eqA[1], eA2 = eqA[2];
            float eB0 = eqB[0], eB1 = eqB[1], eB2 = eqB[2];
            float eC0 = eqC[0], eC1 = eqC[1], eC2 = eqC[2];
            float eD0 = eqD[0], eD1 = eqD[1], eD2 = eqD[2];
            float4 rdx = *reinterpret_cast<const float4*>(&sh_rd0[e]);
            float4 rdy = *reinterpret_cast<const float4*>(&sh_rd1[e]);
            float4 rdz = *reinterpret_cast<const float4*>(&sh_rd2[e]);

            float WA0 = br0, WA1 = br1, WA2 = br2;
            float WB0 = br0, WB1 = br1, WB2 = br2;
            float WC0 = br0, WC1 = br1, WC2 = br2;
            float WD0 = br0, WD1 = br1, WD2 = br2;
#pragma unroll
            for (int k = 0; k < N_RBF; k++) {
                float4 r4 = *reinterpret_cast<const float4*>(&sh_rbf[k][e]);  // broadcast LDS.128
                WA0 = fmaf(r4.x, wr0[k], WA0);
                WA1 = fmaf(r4.x, wr1[k], WA1);
                WA2 = fmaf(r4.x, wr2[k], WA2);
                WB0 = fmaf(r4.y, wr0[k], WB0);
                WB1 = fmaf(r4.y, wr1[k], WB1);
                WB2 = fmaf(r4.y, wr2[k], WB2);
                WC0 = fmaf(r4.z, wr0[k], WC0);
                WC1 = fmaf(r4.z, wr1[k], WC1);
                WC2 = fmaf(r4.z, wr2[k], WC2);
                WD0 = fmaf(r4.w, wr0[k], WD0);
                WD1 = fmaf(r4.w, wr1[k], WD1);
                WD2 = fmaf(r4.w, wr2[k], WD2);
            }
            // combine quad
            float sA1 = pA1 * WA1, sA2 = pA2 * WA2;
            float sB1 = pB1 * WB1, sB2 = pB2 * WB2;
            float sC1 = pC1 * WC1, sC2 = pC2 * WC2;
            float sD1 = pD1 * WD1, sD2 = pD2 * WD2;
            acc0 = fmaf(pA0, WA0, acc0);
            acc0 = fmaf(pB0, WB0, acc0);
            acc0 = fmaf(pC0, WC0, acc0);
            acc0 = fmaf(pD0, WD0, acc0);
            aq0 = fmaf(eA0, sA1, fmaf(sA2, rdx.x, aq0));
            aq1 = fmaf(eA1, sA1, fmaf(sA2, rdy.x, aq1));
            aq2 = fmaf(eA2, sA1, fmaf(sA2, rdz.x, aq2));
            aq0 = fmaf(eB0, sB1, fmaf(sB2, rdx.y, aq0));
            aq1 = fmaf(eB1, sB1, fmaf(sB2, rdy.y, aq1));
            aq2 = fmaf(eB2, sB1, fmaf(sB2, rdz.y, aq2));
            aq0 = fmaf(eC0, sC1, fmaf(sC2, rdx.z, aq0));
            aq1 = fmaf(eC1, sC1, fmaf(sC2, rdy.z, aq1));
            aq2 = fmaf(eC2, sC1, fmaf(sC2, rdz.z, aq2));
            aq0 = fmaf(eD0, sD1, fmaf(sD2, rdx.w, aq0));
            aq1 = fmaf(eD1, sD1, fmaf(sD2, rdy.w, aq1));
            aq2 = fmaf(eD2, sD1, fmaf(sD2, rdz.w, aq2));
        }
        // phase 2b: tail edges (scalar)
        for (int e = nch4; e < nch; e++) {
            const float* ph = g_phi + sh_typ[e] * F3;
            int s = sh_src[e];
            const float* eqs = eq + (size_t)s * F3 + f * 3;
            float p0 = ph[f];
            float p1 = ph[F_DIM + f];
            float p2 = ph[2 * F_DIM + f];
            float q0 = eqs[0], q1 = eqs[1], q2 = eqs[2];
            float W0 = br0, W1 = br1, W2 = br2;
#pragma unroll
            for (int k = 0; k < N_RBF; k++) {
                float r = sh_rbf[k][e];
                W0 = fmaf(r, wr0[k], W0);
                W1 = fmaf(r, wr1[k], W1);
                W2 = fmaf(r, wr2[k], W2);
            }
            float s1v = p1 * W1;
            float s2v = p2 * W2;
            acc0 = fmaf(p0, W0, acc0);
            aq0 = fmaf(q0, s1v, fmaf(s2v, sh_rd0[e], aq0));
            aq1 = fmaf(q1, s1v, fmaf(s2v, sh_rd1[e], aq1));
            aq2 = fmaf(q2, s1v, fmaf(s2v, sh_rd2[e], aq2));
        }
        __syncthreads();
    }

    // epilogue: out = input + delta (written exactly once, no atomics)
    out_emb[node * F_DIM + f] = emb_table[zi * F_DIM + f] + acc0;
    float*       oe = out_eq + (size_t)node * F3 + f * 3;
    const float* ei = eq     + (size_t)node * F3 + f * 3;
    oe[0] = ei[0] + aq0;
    oe[1] = ei[1] + aq1;
    oe[2] = ei[2] + aq2;
}

// ---------------------------------------------------------
extern "C" void kernel_launch(void* const* d_in, const int* in_sizes, int n_in,
                              void* d_out, int out_size) {
    const float* pos       = (const float*)d_in[0];
    const float* eq        = (const float*)d_in[1];
    const float* emb_table = (const float*)d_in[2];
    const float* w_phi1    = (const float*)d_in[3];
    const float* b_phi1    = (const float*)d_in[4];
    const float* w_phi2    = (const float*)d_in[5];
    const float* b_phi2    = (const float*)d_in[6];
    const float* w_rbf     = (const float*)d_in[7];
    const float* b_rbf     = (const float*)d_in[8];
    const int*   z         = (const int*)d_in[9];
    const int*   edge_src  = (const int*)d_in[10];
    const int*   edge_dst  = (const int*)d_in[11];

    float* out     = (float*)d_out;
    float* out_emb = out;                                  // [N, 128]
    float* out_eq  = out + (size_t)N_NODES * F_DIM;        // [N, 128, 3]

    pre_kernel<<<HIST_NB + PHI_NB, 256>>>(edge_dst, emb_table, w_phi1, b_phi1,
                                          w_phi2, b_phi2);
    scan_kernel<<<SCAN_NB, SCAN_B>>>();
    sg_kernel<<<HIST_NB, 256>>>(pos, z, edge_src, edge_dst);
    main_kernel<<<N_NODES, 128>>>(eq, emb_table, w_rbf, b_rbf, z,
                                  out_emb, out_eq);
}

// round 11
// speedup vs baseline: 1.4452x; 1.1690x over previous
#include <cuda_runtime.h>
#include <math.h>

#define N_NODES 50000
#define N_EDGES 400000
#define F_DIM   128
#define N_TYPES 100
#define N_RBF   20
#define CUTOFF  5.0f
#define F3      (3 * F_DIM)   // 384

#define SCAN_B  256
#define SCAN_NB ((N_NODES + SCAN_B - 1) / SCAN_B)   // 196
#define HIST_NB ((N_EDGES + 255) / 256)             // 1563
#define PHI_NB  (N_TYPES / 2)                       // 50

#define NPB     16                                  // nodes per main block
#define MAIN_NB (N_NODES / NPB)                     // 3125 (divides exactly)
#define E_MAX   (N_EDGES + 3 * N_NODES + 16)        // padded edge capacity

typedef unsigned long long ull;

// -------- device scratch (no allocations allowed; zero-initialized at load) --------
__device__ int   g_count[N_NODES];        // re-zeroed by scan_kernel each call
__device__ int   g_start[N_NODES + 1];    // PADDED segment starts (multiples of 4)
__device__ int   g_cursor[N_NODES];
__device__ ull   g_scan_state[SCAN_NB];   // re-zeroed by sg_kernel each call
__device__ float g_phi[(N_TYPES + 1) * F3];  // row N_TYPES stays all-zero (pad sentinel)

// per-edge packed row (dst-sorted order): [0..19]=rbf, [20..22]=rel*dist,
// [23]=pad, [24]=src bits, [25]=typ bits, [26..31]=pad  => 128 bytes
struct __align__(16) EdgeRow { float v[32]; };
__device__ EdgeRow g_edat[E_MAX];

// ---------------------------------------------------------
// Launch 0 (pre): hist blocks count edge_dst; phi blocks compute the MLP table.
__global__ void pre_kernel(const int* __restrict__ edge_dst,
                           const float* __restrict__ emb_table,
                           const float* __restrict__ w1, const float* __restrict__ b1,
                           const float* __restrict__ w2, const float* __restrict__ b2) {
    if (blockIdx.x < HIST_NB) {
        int e = blockIdx.x * 256 + threadIdx.x;
        if (e < N_EDGES) atomicAdd(&g_count[edge_dst[e]], 1);
        return;
    }
    // phi: 2 atom types per block (each 128-thread half does one type)
    int bb = blockIdx.x - HIST_NB;          // 0..49
    int half = threadIdx.x >> 7;            // 0/1
    int t = bb * 2 + half;                  // atom type
    int f = threadIdx.x & 127;
    __shared__ float es[2][F_DIM];
    __shared__ float hs[2][F_DIM];
    es[half][f] = emb_table[t * F_DIM + f];
    __syncthreads();
    float h = b1[f];
#pragma unroll 8
    for (int k = 0; k < F_DIM; k++)
        h = fmaf(es[half][k], w1[k * F_DIM + f], h);
    h = h / (1.0f + expf(-h));   // silu
    hs[half][f] = h;
    __syncthreads();
    float o0 = b2[f], o1 = b2[F_DIM + f], o2 = b2[2 * F_DIM + f];
#pragma unroll 8
    for (int k = 0; k < F_DIM; k++) {
        float hk = hs[half][k];
        const float* w2r = w2 + k * F3;
        o0 = fmaf(hk, w2r[f],             o0);
        o1 = fmaf(hk, w2r[F_DIM + f],     o1);
        o2 = fmaf(hk, w2r[2 * F_DIM + f], o2);
    }
    g_phi[t * F3 + f]             = o0;
    g_phi[t * F3 + F_DIM + f]     = o1;
    g_phi[t * F3 + 2 * F_DIM + f] = o2;
}

// ---------------------------------------------------------
// Launch 1: decoupled-lookback exclusive scan of PADDED counts
// ((cnt+3)&~3) -> g_start, g_cursor. Re-zeroes g_count; writes inert pad rows.
__global__ void scan_kernel() {
    __shared__ int wsum[SCAN_B / 32];
    __shared__ int s_prefix;
    int t = threadIdx.x;
    int b = blockIdx.x;
    int i = b * SCAN_B + t;
    int v = 0, pc = 0;
    if (i < N_NODES) {
        v = g_count[i];
        g_count[i] = 0;
        pc = (v + 3) & ~3;
    }

    int sv = pc;
    for (int off = 1; off < 32; off <<= 1) {
        int u = __shfl_up_sync(0xffffffffu, sv, off);
        if ((t & 31) >= off) sv += u;
    }
    if ((t & 31) == 31) wsum[t >> 5] = sv;
    __syncthreads();
    if (t < SCAN_B / 32) {
        int s = wsum[t];
        for (int off = 1; off < SCAN_B / 32; off <<= 1) {
            int u = __shfl_up_sync(0xffu, s, off);
            if (t >= off) s += u;
        }
        wsum[t] = s;
    }
    __syncthreads();
    int warp = t >> 5;
    int incl = sv + ((warp > 0) ? wsum[warp - 1] : 0);
    int total = wsum[SCAN_B / 32 - 1];

    if (t == 0) {
        if (b == 0) {
            atomicExch(&g_scan_state[0], ((ull)total << 2) | 2ULL);
            s_prefix = 0;
        } else {
            atomicExch(&g_scan_state[b], ((ull)total << 2) | 1ULL);
            int prefix = 0;
            int j = b - 1;
            while (j >= 0) {
                ull st;
                do { st = atomicAdd(&g_scan_state[j], 0ULL); } while ((st & 3ULL) == 0ULL);
                prefix += (int)(st >> 2);
                if ((st & 3ULL) == 2ULL) break;
                j--;
            }
            atomicExch(&g_scan_state[b], ((ull)(prefix + total) << 2) | 2ULL);
            s_prefix = prefix;
        }
        if (b == SCAN_NB - 1) g_start[N_NODES] = s_prefix + total;
    }
    __syncthreads();
    int excl = s_prefix + incl - pc;
    if (i < N_NODES) {
        g_start[i]  = excl;
        g_cursor[i] = excl;
        // inert pad rows: rbf=0, rd=0, src=0, typ=N_TYPES (all-zero phi row)
        for (int j = excl + v; j < excl + pc; j++) {
            float4* d4 = reinterpret_cast<float4*>(g_edat[j].v);
            float4 z4 = make_float4(0.f, 0.f, 0.f, 0.f);
#pragma unroll
            for (int q = 0; q < 8; q++) d4[q] = z4;
            d4[6] = make_float4(0.f, __int_as_float(N_TYPES), 0.f, 0.f);
        }
    }
}

// ---------------------------------------------------------
// Launch 2: fused scatter + geometry; also re-zeroes g_scan_state.
__global__ void sg_kernel(const float* __restrict__ pos,
                          const int*   __restrict__ z,
                          const int*   __restrict__ edge_src,
                          const int*   __restrict__ edge_dst) {
    int e = blockIdx.x * blockDim.x + threadIdx.x;
    if (e < SCAN_NB) g_scan_state[e] = 0ULL;
    if (e >= N_EDGES) return;
    int s = __ldg(&edge_src[e]);
    int d = __ldg(&edge_dst[e]);
    int p = atomicAdd(&g_cursor[d], 1);
    int ty = __ldg(&z[s]);
    float rx = __ldg(&pos[d * 3 + 0]) - __ldg(&pos[s * 3 + 0]);
    float ry = __ldg(&pos[d * 3 + 1]) - __ldg(&pos[s * 3 + 1]);
    float rz = __ldg(&pos[d * 3 + 2]) - __ldg(&pos[s * 3 + 2]);
    float dist = sqrtf(rx * rx + ry * ry + rz * rz);
    float inv  = 1.0f / dist;

    float row[32];
    float a = 3.14159265358979323846f * dist * (1.0f / CUTOFF);
    float s1, c1;
    sincosf(a, &s1, &c1);
    float twoc = 2.0f * c1;
    float sp = 0.0f, sc = s1;          // sin(0), sin(a)
#pragma unroll
    for (int k = 0; k < N_RBF; k++) {  // sin((k+1)a), stable Chebyshev recurrence
        row[k] = sc * inv;
        float nx = twoc * sc - sp;
        sp = sc; sc = nx;
    }
    row[20] = rx * dist;
    row[21] = ry * dist;
    row[22] = rz * dist;
    row[23] = 0.0f;
    row[24] = __int_as_float(s);
    row[25] = __int_as_float(ty);
    row[26] = row[27] = row[28] = row[29] = row[30] = row[31] = 0.0f;

    float4* dst4 = reinterpret_cast<float4*>(g_edat[p].v);
    const float4* src4 = reinterpret_cast<const float4*>(row);
#pragma unroll
    for (int j = 0; j < 8; j++) dst4[j] = src4[j];
}

// ---------------------------------------------------------
// Launch 3 (PROFILED): main. One block per NPB=16 consecutive nodes.
// Weights loaded once per block; contiguous padded edge range staged in
// 128-edge chunks; every per-node run is a whole number of aligned quads.
__global__ __launch_bounds__(128, 4)
void main_kernel(const float* __restrict__ eq,
                 const float* __restrict__ emb_table,
                 const float* __restrict__ w_rbf,
                 const float* __restrict__ b_rbf,
                 const int*   __restrict__ z,
                 float* __restrict__ out_emb,
                 float* __restrict__ out_eq) {
    int f = threadIdx.x;
    int nb0 = blockIdx.x * NPB;

    __shared__ int s_bnd[NPB + 1];
    if (f <= NPB) s_bnd[f] = g_start[nb0 + f];

    // per-thread w_rbf columns in registers (60 regs) — once per 16 nodes
    float wr0[N_RBF], wr1[N_RBF], wr2[N_RBF];
#pragma unroll
    for (int k = 0; k < N_RBF; k++) {
        const float* row = w_rbf + k * F3;
        wr0[k] = row[f];
        wr1[k] = row[F_DIM + f];
        wr2[k] = row[2 * F_DIM + f];
    }
    const float br0 = b_rbf[f], br1 = b_rbf[F_DIM + f], br2 = b_rbf[2 * F_DIM + f];

    __shared__ __align__(16) float sh_rbf[N_RBF][128];
    __shared__ __align__(16) float sh_rd0[128], sh_rd1[128], sh_rd2[128];
    __shared__ __align__(16) int   sh_src[128];
    __shared__ __align__(16) int   sh_typ[128];

    __syncthreads();
    const int eAll0 = s_bnd[0];
    const int eAll1 = s_bnd[NPB];
    int nd = 0;   // local node index 0..NPB-1
    float acc0 = 0.f, aq0 = 0.f, aq1 = 0.f, aq2 = 0.f;

    for (int base = eAll0; base < eAll1; base += 128) {
        int nch = min(128, eAll1 - base);
        // phase 1: bulk-load pre-staged rows, transpose into smem
        if (f < nch) {
            const float4* row = reinterpret_cast<const float4*>(g_edat[base + f].v);
            float4 a0 = __ldg(row + 0);
            float4 a1 = __ldg(row + 1);
            float4 a2 = __ldg(row + 2);
            float4 a3 = __ldg(row + 3);
            float4 a4 = __ldg(row + 4);
            float4 rd = __ldg(row + 5);
            float4 mt = __ldg(row + 6);
            sh_rbf[0][f]  = a0.x; sh_rbf[1][f]  = a0.y; sh_rbf[2][f]  = a0.z; sh_rbf[3][f]  = a0.w;
            sh_rbf[4][f]  = a1.x; sh_rbf[5][f]  = a1.y; sh_rbf[6][f]  = a1.z; sh_rbf[7][f]  = a1.w;
            sh_rbf[8][f]  = a2.x; sh_rbf[9][f]  = a2.y; sh_rbf[10][f] = a2.z; sh_rbf[11][f] = a2.w;
            sh_rbf[12][f] = a3.x; sh_rbf[13][f] = a3.y; sh_rbf[14][f] = a3.z; sh_rbf[15][f] = a3.w;
            sh_rbf[16][f] = a4.x; sh_rbf[17][f] = a4.y; sh_rbf[18][f] = a4.z; sh_rbf[19][f] = a4.w;
            sh_rd0[f] = rd.x;
            sh_rd1[f] = rd.y;
            sh_rd2[f] = rd.z;
            sh_src[f] = __float_as_int(mt.x);
            sh_typ[f] = __float_as_int(mt.y);
        }
        __syncthreads();

        // phase 2: walk node runs inside this chunk (all runs quad-aligned)
        int ec = 0;
        while (ec < nch) {
            int ndend = s_bnd[nd + 1];                       // global padded end
            int run = min(ndend - base, nch) - ec;           // multiple of 4
            for (int e = ec; e < ec + run; e += 4) {
                int4 s4 = *reinterpret_cast<const int4*>(&sh_src[e]);
                int4 t4 = *reinterpret_cast<const int4*>(&sh_typ[e]);
                const float* phA = g_phi + t4.x * F3;
                const float* phB = g_phi + t4.y * F3;
                const float* phC = g_phi + t4.z * F3;
                const float* phD = g_phi + t4.w * F3;
                float pA0 = phA[f], pA1 = phA[F_DIM + f], pA2 = phA[2 * F_DIM + f];
                float pB0 = phB[f], pB1 = phB[F_DIM + f], pB2 = phB[2 * F_DIM + f];
                float pC0 = phC[f], pC1 = phC[F_DIM + f], pC2 = phC[2 * F_DIM + f];
                float pD0 = phD[f], pD1 = phD[F_DIM + f], pD2 = phD[2 * F_DIM + f];
                const float* eqA = eq + (size_t)s4.x * F3 + f * 3;
                const float* eqB = eq + (size_t)s4.y * F3 + f * 3;
                const float* eqC = eq + (size_t)s4.z * F3 + f * 3;
                const float* eqD = eq + (size_t)s4.w * F3 + f * 3;
                float eA0 = eqA[0], eA1 = eqA[1], eA2 = eqA[2];
                float eB0 = eqB[0], eB1 = eqB[1], eB2 = eqB[2];
                float eC0 = eqC[0], eC1 = eqC[1], eC2 = eqC[2];
                float eD0 = eqD[0], eD1 = eqD[1], eD2 = eqD[2];
                float4 rdx = *reinterpret_cast<const float4*>(&sh_rd0[e]);
                float4 rdy = *reinterpret_cast<const float4*>(&sh_rd1[e]);
                float4 rdz = *reinterpret_cast<const float4*>(&sh_rd2[e]);

                float WA0 = br0, WA1 = br1, WA2 = br2;
                float WB0 = br0, WB1 = br1, WB2 = br2;
                float WC0 = br0, WC1 = br1, WC2 = br2;
                float WD0 = br0, WD1 = br1, WD2 = br2;
#pragma unroll
                for (int k = 0; k < N_RBF; k++) {
                    float4 r4 = *reinterpret_cast<const float4*>(&sh_rbf[k][e]);
                    WA0 = fmaf(r4.x, wr0[k], WA0);
                    WA1 = fmaf(r4.x, wr1[k], WA1);
                    WA2 = fmaf(r4.x, wr2[k], WA2);
                    WB0 = fmaf(r4.y, wr0[k], WB0);
                    WB1 = fmaf(r4.y, wr1[k], WB1);
                    WB2 = fmaf(r4.y, wr2[k], WB2);
                    WC0 = fmaf(r4.z, wr0[k], WC0);
                    WC1 = fmaf(r4.z, wr1[k], WC1);
                    WC2 = fmaf(r4.z, wr2[k], WC2);
                    WD0 = fmaf(r4.w, wr0[k], WD0);
                    WD1 = fmaf(r4.w, wr1[k], WD1);
                    WD2 = fmaf(r4.w, wr2[k], WD2);
                }
                float sA1 = pA1 * WA1, sA2 = pA2 * WA2;
                float sB1 = pB1 * WB1, sB2 = pB2 * WB2;
                float sC1 = pC1 * WC1, sC2 = pC2 * WC2;
                float sD1 = pD1 * WD1, sD2 = pD2 * WD2;
                acc0 = fmaf(pA0, WA0, acc0);
                acc0 = fmaf(pB0, WB0, acc0);
                acc0 = fmaf(pC0, WC0, acc0);
                acc0 = fmaf(pD0, WD0, acc0);
                aq0 = fmaf(eA0, sA1, fmaf(sA2, rdx.x, aq0));
                aq1 = fmaf(eA1, sA1, fmaf(sA2, rdy.x, aq1));
                aq2 = fmaf(eA2, sA1, fmaf(sA2, rdz.x, aq2));
                aq0 = fmaf(eB0, sB1, fmaf(sB2, rdx.y, aq0));
                aq1 = fmaf(eB1, sB1, fmaf(sB2, rdy.y, aq1));
                aq2 = fmaf(eB2, sB1, fmaf(sB2, rdz.y, aq2));
                aq0 = fmaf(eC0, sC1, fmaf(sC2, rdx.z, aq0));
                aq1 = fmaf(eC1, sC1, fmaf(sC2, rdy.z, aq1));
                aq2 = fmaf(eC2, sC1, fmaf(sC2, rdz.z, aq2));
                aq0 = fmaf(eD0, sD1, fmaf(sD2, rdx.w, aq0));
                aq1 = fmaf(eD1, sD1, fmaf(sD2, rdy.w, aq1));
                aq2 = fmaf(eD2, sD1, fmaf(sD2, rdz.w, aq2));
            }
            ec += run;
            if (base + ec == ndend) {
                // close node nb0+nd
                int node = nb0 + nd;
                int zi = __ldg(&z[node]);
                out_emb[node * F_DIM + f] = emb_table[zi * F_DIM + f] + acc0;
                const float* ei = eq     + (size_t)node * F3 + f * 3;
                float*       oe = out_eq + (size_t)node * F3 + f * 3;
                oe[0] = ei[0] + aq0;
                oe[1] = ei[1] + aq1;
                oe[2] = ei[2] + aq2;
                acc0 = aq0 = aq1 = aq2 = 0.f;
                nd++;
            }
        }
        __syncthreads();
    }

    // flush trailing empty nodes (zero-degree): out = input
    while (nd < NPB) {
        int node = nb0 + nd;
        int zi = __ldg(&z[node]);
        out_emb[node * F_DIM + f] = emb_table[zi * F_DIM + f];
        const float* ei = eq     + (size_t)node * F3 + f * 3;
        float*       oe = out_eq + (size_t)node * F3 + f * 3;
        oe[0] = ei[0];
        oe[1] = ei[1];
        oe[2] = ei[2];
        nd++;
    }
}

// ---------------------------------------------------------
extern "C" void kernel_launch(void* const* d_in, const int* in_sizes, int n_in,
                              void* d_out, int out_size) {
    const float* pos       = (const float*)d_in[0];
    const float* eq        = (const float*)d_in[1];
    const float* emb_table = (const float*)d_in[2];
    const float* w_phi1    = (const float*)d_in[3];
    const float* b_phi1    = (const float*)d_in[4];
    const float* w_phi2    = (const float*)d_in[5];
    const float* b_phi2    = (const float*)d_in[6];
    const float* w_rbf     = (const float*)d_in[7];
    const float* b_rbf     = (const float*)d_in[8];
    const int*   z         = (const int*)d_in[9];
    const int*   edge_src  = (const int*)d_in[10];
    const int*   edge_dst  = (const int*)d_in[11];

    float* out     = (float*)d_out;
    float* out_emb = out;                                  // [N, 128]
    float* out_eq  = out + (size_t)N_NODES * F_DIM;        // [N, 128, 3]

    pre_kernel<<<HIST_NB + PHI_NB, 256>>>(edge_dst, emb_table, w_phi1, b_phi1,
                                          w_phi2, b_phi2);
    scan_kernel<<<SCAN_NB, SCAN_B>>>();
    sg_kernel<<<HIST_NB, 256>>>(pos, z, edge_src, edge_dst);
    main_kernel<<<MAIN_NB, 128>>>(eq, emb_table, w_rbf, b_rbf, z,
                                  out_emb, out_eq);
}

// round 12
// speedup vs baseline: 1.5812x; 1.0941x over previous
#include <cuda_runtime.h>
#include <math.h>

#define N_NODES 50000
#define N_EDGES 400000
#define F_DIM   128
#define N_TYPES 100
#define N_RBF   20
#define CUTOFF  5.0f
#define F3      (3 * F_DIM)   // 384

#define SCAN_B  256
#define SCAN_NB ((N_NODES + SCAN_B - 1) / SCAN_B)   // 196
#define HIST_NB ((N_EDGES + 255) / 256)             // 1563
#define PHI_NB  (N_TYPES / 2)                       // 50

#define NPB     25                                  // nodes per main block
#define MAIN_NB (N_NODES / NPB)                     // 2000 (divides exactly)
#define E_MAX   (N_EDGES + 3 * N_NODES + 16)        // padded edge capacity

typedef unsigned long long ull;

// -------- device scratch (no allocations allowed; zero-initialized at load) --------
__device__ int   g_count[N_NODES];        // re-zeroed by scan_kernel each call
__device__ int   g_start[N_NODES + 1];    // PADDED segment starts (multiples of 4)
__device__ int   g_cursor[N_NODES];
__device__ ull   g_scan_state[SCAN_NB];   // re-zeroed by sg_kernel each call
__device__ float g_phi[(N_TYPES + 1) * F3];  // row N_TYPES stays all-zero (pad sentinel)

// per-edge packed row (dst-sorted order), 32 bytes:
// [0]=sin(a) [1]=cos(a) [2]=1/dist [3]=rd.x | [4]=rd.y [5]=rd.z [6]=src bits [7]=typ bits
struct __align__(16) EdgeRow { float v[8]; };
__device__ EdgeRow g_edat[E_MAX];         // 13.9 MB

// ---------------------------------------------------------
// Launch 0 (pre): hist blocks count edge_dst; phi blocks compute the MLP table.
__global__ void pre_kernel(const int* __restrict__ edge_dst,
                           const float* __restrict__ emb_table,
                           const float* __restrict__ w1, const float* __restrict__ b1,
                           const float* __restrict__ w2, const float* __restrict__ b2) {
    if (blockIdx.x < HIST_NB) {
        int e = blockIdx.x * 256 + threadIdx.x;
        if (e < N_EDGES) atomicAdd(&g_count[edge_dst[e]], 1);
        return;
    }
    // phi: 2 atom types per block (each 128-thread half does one type)
    int bb = blockIdx.x - HIST_NB;          // 0..49
    int half = threadIdx.x >> 7;            // 0/1
    int t = bb * 2 + half;                  // atom type
    int f = threadIdx.x & 127;
    __shared__ float es[2][F_DIM];
    __shared__ float hs[2][F_DIM];
    es[half][f] = emb_table[t * F_DIM + f];
    __syncthreads();
    float h = b1[f];
#pragma unroll 8
    for (int k = 0; k < F_DIM; k++)
        h = fmaf(es[half][k], w1[k * F_DIM + f], h);
    h = h / (1.0f + expf(-h));   // silu
    hs[half][f] = h;
    __syncthreads();
    float o0 = b2[f], o1 = b2[F_DIM + f], o2 = b2[2 * F_DIM + f];
#pragma unroll 8
    for (int k = 0; k < F_DIM; k++) {
        float hk = hs[half][k];
        const float* w2r = w2 + k * F3;
        o0 = fmaf(hk, w2r[f],             o0);
        o1 = fmaf(hk, w2r[F_DIM + f],     o1);
        o2 = fmaf(hk, w2r[2 * F_DIM + f], o2);
    }
    g_phi[t * F3 + f]             = o0;
    g_phi[t * F3 + F_DIM + f]     = o1;
    g_phi[t * F3 + 2 * F_DIM + f] = o2;
}

// ---------------------------------------------------------
// Launch 1: decoupled-lookback exclusive scan of PADDED counts
// ((cnt+3)&~3) -> g_start, g_cursor. Re-zeroes g_count; writes inert pad rows.
__global__ void scan_kernel() {
    __shared__ int wsum[SCAN_B / 32];
    __shared__ int s_prefix;
    int t = threadIdx.x;
    int b = blockIdx.x;
    int i = b * SCAN_B + t;
    int v = 0, pc = 0;
    if (i < N_NODES) {
        v = g_count[i];
        g_count[i] = 0;
        pc = (v + 3) & ~3;
    }

    int sv = pc;
    for (int off = 1; off < 32; off <<= 1) {
        int u = __shfl_up_sync(0xffffffffu, sv, off);
        if ((t & 31) >= off) sv += u;
    }
    if ((t & 31) == 31) wsum[t >> 5] = sv;
    __syncthreads();
    if (t < SCAN_B / 32) {
        int s = wsum[t];
        for (int off = 1; off < SCAN_B / 32; off <<= 1) {
            int u = __shfl_up_sync(0xffu, s, off);
            if (t >= off) s += u;
        }
        wsum[t] = s;
    }
    __syncthreads();
    int warp = t >> 5;
    int incl = sv + ((warp > 0) ? wsum[warp - 1] : 0);
    int total = wsum[SCAN_B / 32 - 1];

    if (t == 0) {
        if (b == 0) {
            atomicExch(&g_scan_state[0], ((ull)total << 2) | 2ULL);
            s_prefix = 0;
        } else {
            atomicExch(&g_scan_state[b], ((ull)total << 2) | 1ULL);
            int prefix = 0;
            int j = b - 1;
            while (j >= 0) {
                ull st;
                do { st = atomicAdd(&g_scan_state[j], 0ULL); } while ((st & 3ULL) == 0ULL);
                prefix += (int)(st >> 2);
                if ((st & 3ULL) == 2ULL) break;
                j--;
            }
            atomicExch(&g_scan_state[b], ((ull)(prefix + total) << 2) | 2ULL);
            s_prefix = prefix;
        }
        if (b == SCAN_NB - 1) g_start[N_NODES] = s_prefix + total;
    }
    __syncthreads();
    int excl = s_prefix + incl - pc;
    if (i < N_NODES) {
        g_start[i]  = excl;
        g_cursor[i] = excl;
        // inert pad rows: sin=cos=inv=0 -> rbf all zero; typ=N_TYPES (zero phi row)
        for (int j = excl + v; j < excl + pc; j++) {
            float4* d4 = reinterpret_cast<float4*>(g_edat[j].v);
            d4[0] = make_float4(0.f, 0.f, 0.f, 0.f);
            d4[1] = make_float4(0.f, 0.f, 0.f, __int_as_float(N_TYPES));
        }
    }
}

// ---------------------------------------------------------
// Launch 2: fused scatter + geometry (32B rows); also re-zeroes g_scan_state.
__global__ void sg_kernel(const float* __restrict__ pos,
                          const int*   __restrict__ z,
                          const int*   __restrict__ edge_src,
                          const int*   __restrict__ edge_dst) {
    int e = blockIdx.x * blockDim.x + threadIdx.x;
    if (e < SCAN_NB) g_scan_state[e] = 0ULL;
    if (e >= N_EDGES) return;
    int s = __ldg(&edge_src[e]);
    int d = __ldg(&edge_dst[e]);
    int p = atomicAdd(&g_cursor[d], 1);
    int ty = __ldg(&z[s]);
    float rx = __ldg(&pos[d * 3 + 0]) - __ldg(&pos[s * 3 + 0]);
    float ry = __ldg(&pos[d * 3 + 1]) - __ldg(&pos[s * 3 + 1]);
    float rz = __ldg(&pos[d * 3 + 2]) - __ldg(&pos[s * 3 + 2]);
    float dist = sqrtf(rx * rx + ry * ry + rz * rz);
    float inv  = 1.0f / dist;

    float a = 3.14159265358979323846f * dist * (1.0f / CUTOFF);
    float s1, c1;
    sincosf(a, &s1, &c1);

    float4* dst4 = reinterpret_cast<float4*>(g_edat[p].v);
    dst4[0] = make_float4(s1, c1, inv, rx * dist);
    dst4[1] = make_float4(ry * dist, rz * dist, __int_as_float(s), __int_as_float(ty));
}

// ---------------------------------------------------------
// Launch 3 (PROFILED): main. One block per NPB=25 consecutive nodes.
// Phase 1 regenerates rbf[20] from (sin,cos,inv) via Chebyshev recurrence.
__global__ __launch_bounds__(128, 4)
void main_kernel(const float* __restrict__ eq,
                 const float* __restrict__ emb_table,
                 const float* __restrict__ w_rbf,
                 const float* __restrict__ b_rbf,
                 const int*   __restrict__ z,
                 float* __restrict__ out_emb,
                 float* __restrict__ out_eq) {
    int f = threadIdx.x;
    int nb0 = blockIdx.x * NPB;

    __shared__ int s_bnd[NPB + 1];
    if (f <= NPB) s_bnd[f] = g_start[nb0 + f];

    // per-thread w_rbf columns in registers (60 regs) — once per 25 nodes
    float wr0[N_RBF], wr1[N_RBF], wr2[N_RBF];
#pragma unroll
    for (int k = 0; k < N_RBF; k++) {
        const float* row = w_rbf + k * F3;
        wr0[k] = row[f];
        wr1[k] = row[F_DIM + f];
        wr2[k] = row[2 * F_DIM + f];
    }
    const float br0 = b_rbf[f], br1 = b_rbf[F_DIM + f], br2 = b_rbf[2 * F_DIM + f];

    __shared__ __align__(16) float sh_rbf[N_RBF][128];
    __shared__ __align__(16) float sh_rd0[128], sh_rd1[128], sh_rd2[128];
    __shared__ __align__(16) int   sh_src[128];
    __shared__ __align__(16) int   sh_typ[128];

    __syncthreads();
    const int eAll0 = s_bnd[0];
    const int eAll1 = s_bnd[NPB];
    int nd = 0;   // local node index 0..NPB-1
    float acc0 = 0.f, aq0 = 0.f, aq1 = 0.f, aq2 = 0.f;

    for (int base = eAll0; base < eAll1; base += 128) {
        int nch = min(128, eAll1 - base);
        // phase 1: load 32B row, regenerate rbf via recurrence, stage transposed
        if (f < nch) {
            const float4* row = reinterpret_cast<const float4*>(g_edat[base + f].v);
            float4 A = __ldg(row + 0);
            float4 B = __ldg(row + 1);
            float twoc = 2.0f * A.y;
            float inv  = A.z;
            float sp = 0.0f, sc = A.x;     // sin(0), sin(a)
#pragma unroll
            for (int k = 0; k < N_RBF; k++) {
                sh_rbf[k][f] = sc * inv;
                float nx = twoc * sc - sp;
                sp = sc; sc = nx;
            }
            sh_rd0[f] = A.w;
            sh_rd1[f] = B.x;
            sh_rd2[f] = B.y;
            sh_src[f] = __float_as_int(B.z);
            sh_typ[f] = __float_as_int(B.w);
        }
        __syncthreads();

        // phase 2: walk node runs inside this chunk (all runs quad-aligned)
        int ec = 0;
        while (ec < nch) {
            int ndend = s_bnd[nd + 1];                       // global padded end
            int run = min(ndend - base, nch) - ec;           // multiple of 4
            for (int e = ec; e < ec + run; e += 4) {
                int4 s4 = *reinterpret_cast<const int4*>(&sh_src[e]);
                int4 t4 = *reinterpret_cast<const int4*>(&sh_typ[e]);
                const float* phA = g_phi + t4.x * F3;
                const float* phB = g_phi + t4.y * F3;
                const float* phC = g_phi + t4.z * F3;
                const float* phD = g_phi + t4.w * F3;
                float pA0 = phA[f], pA1 = phA[F_DIM + f], pA2 = phA[2 * F_DIM + f];
                float pB0 = phB[f], pB1 = phB[F_DIM + f], pB2 = phB[2 * F_DIM + f];
                float pC0 = phC[f], pC1 = phC[F_DIM + f], pC2 = phC[2 * F_DIM + f];
                float pD0 = phD[f], pD1 = phD[F_DIM + f], pD2 = phD[2 * F_DIM + f];
                const float* eqA = eq + (size_t)s4.x * F3 + f * 3;
                const float* eqB = eq + (size_t)s4.y * F3 + f * 3;
                const float* eqC = eq + (size_t)s4.z * F3 + f * 3;
                const float* eqD = eq + (size_t)s4.w * F3 + f * 3;
                float eA0 = eqA[0], eA1 = eqA[1], eA2 = eqA[2];
                float eB0 = eqB[0], eB1 = eqB[1], eB2 = eqB[2];
                float eC0 = eqC[0], eC1 = eqC[1], eC2 = eqC[2];
                float eD0 = eqD[0], eD1 = eqD[1], eD2 = eqD[2];
                float4 rdx = *reinterpret_cast<const float4*>(&sh_rd0[e]);
                float4 rdy = *reinterpret_cast<const float4*>(&sh_rd1[e]);
                float4 rdz = *reinterpret_cast<const float4*>(&sh_rd2[e]);

                float WA0 = br0, WA1 = br1, WA2 = br2;
                float WB0 = br0, WB1 = br1, WB2 = br2;
                float WC0 = br0, WC1 = br1, WC2 = br2;
                float WD0 = br0, WD1 = br1, WD2 = br2;
#pragma unroll
                for (int k = 0; k < N_RBF; k++) {
                    float4 r4 = *reinterpret_cast<const float4*>(&sh_rbf[k][e]);
                    WA0 = fmaf(r4.x, wr0[k], WA0);
                    WA1 = fmaf(r4.x, wr1[k], WA1);
                    WA2 = fmaf(r4.x, wr2[k], WA2);
                    WB0 = fmaf(r4.y, wr0[k], WB0);
                    WB1 = fmaf(r4.y, wr1[k], WB1);
                    WB2 = fmaf(r4.y, wr2[k], WB2);
                    WC0 = fmaf(r4.z, wr0[k], WC0);
                    WC1 = fmaf(r4.z, wr1[k], WC1);
                    WC2 = fmaf(r4.z, wr2[k], WC2);
                    WD0 = fmaf(r4.w, wr0[k], WD0);
                    WD1 = fmaf(r4.w, wr1[k], WD1);
                    WD2 = fmaf(r4.w, wr2[k], WD2);
                }
                float sA1 = pA1 * WA1, sA2 = pA2 * WA2;
                float sB1 = pB1 * WB1, sB2 = pB2 * WB2;
                float sC1 = pC1 * WC1, sC2 = pC2 * WC2;
                float sD1 = pD1 * WD1, sD2 = pD2 * WD2;
                acc0 = fmaf(pA0, WA0, acc0);
                acc0 = fmaf(pB0, WB0, acc0);
                acc0 = fmaf(pC0, WC0, acc0);
                acc0 = fmaf(pD0, WD0, acc0);
                aq0 = fmaf(eA0, sA1, fmaf(sA2, rdx.x, aq0));
                aq1 = fmaf(eA1, sA1, fmaf(sA2, rdy.x, aq1));
                aq2 = fmaf(eA2, sA1, fmaf(sA2, rdz.x, aq2));
                aq0 = fmaf(eB0, sB1, fmaf(sB2, rdx.y, aq0));
                aq1 = fmaf(eB1, sB1, fmaf(sB2, rdy.y, aq1));
                aq2 = fmaf(eB2, sB1, fmaf(sB2, rdz.y, aq2));
                aq0 = fmaf(eC0, sC1, fmaf(sC2, rdx.z, aq0));
                aq1 = fmaf(eC1, sC1, fmaf(sC2, rdy.z, aq1));
                aq2 = fmaf(eC2, sC1, fmaf(sC2, rdz.z, aq2));
                aq0 = fmaf(eD0, sD1, fmaf(sD2, rdx.w, aq0));
                aq1 = fmaf(eD1, sD1, fmaf(sD2, rdy.w, aq1));
                aq2 = fmaf(eD2, sD1, fmaf(sD2, rdz.w, aq2));
            }
            ec += run;
            if (base + ec == ndend) {
                // close node nb0+nd
                int node = nb0 + nd;
                int zi = __ldg(&z[node]);
                out_emb[node * F_DIM + f] = emb_table[zi * F_DIM + f] + acc0;
                const float* ei = eq     + (size_t)node * F3 + f * 3;
                float*       oe = out_eq + (size_t)node * F3 + f * 3;
                oe[0] = ei[0] + aq0;
                oe[1] = ei[1] + aq1;
                oe[2] = ei[2] + aq2;
                acc0 = aq0 = aq1 = aq2 = 0.f;
                nd++;
            }
        }
        __syncthreads();
    }

    // flush trailing empty nodes (zero-degree): out = input
    while (nd < NPB) {
        int node = nb0 + nd;
        int zi = __ldg(&z[node]);
        out_emb[node * F_DIM + f] = emb_table[zi * F_DIM + f];
        const float* ei = eq     + (size_t)node * F3 + f * 3;
        float*       oe = out_eq + (size_t)node * F3 + f * 3;
        oe[0] = ei[0];
        oe[1] = ei[1];
        oe[2] = ei[2];
        nd++;
    }
}

// ---------------------------------------------------------
extern "C" void kernel_launch(void* const* d_in, const int* in_sizes, int n_in,
                              void* d_out, int out_size) {
    const float* pos       = (const float*)d_in[0];
    const float* eq        = (const float*)d_in[1];
    const float* emb_table = (const float*)d_in[2];
    const float* w_phi1    = (const float*)d_in[3];
    const float* b_phi1    = (const float*)d_in[4];
    const float* w_phi2    = (const float*)d_in[5];
    const float* b_phi2    = (const float*)d_in[6];
    const float* w_rbf     = (const float*)d_in[7];
    const float* b_rbf     = (const float*)d_in[8];
    const int*   z         = (const int*)d_in[9];
    const int*   edge_src  = (const int*)d_in[10];
    const int*   edge_dst  = (const int*)d_in[11];

    float* out     = (float*)d_out;
    float* out_emb = out;                                  // [N, 128]
    float* out_eq  = out + (size_t)N_NODES * F_DIM;        // [N, 128, 3]

    pre_kernel<<<HIST_NB + PHI_NB, 256>>>(edge_dst, emb_table, w_phi1, b_phi1,
                                          w_phi2, b_phi2);
    scan_kernel<<<SCAN_NB, SCAN_B>>>();
    sg_kernel<<<HIST_NB, 256>>>(pos, z, edge_src, edge_dst);
    main_kernel<<<MAIN_NB, 128>>>(eq, emb_table, w_rbf, b_rbf, z,
                                  out_emb, out_eq);
}